// round 15
// baseline (speedup 1.0000x reference)
#include <cuda_runtime.h>
#include <cuda_fp16.h>

typedef unsigned int uint32;

#define BB 8
#define NN 2048
#define FF 256
#define M_TOT (BB*NN)   // 16384
#define PITCH 80        // gemm1 tile pitch (32 fp16 cols)
#define PITCH2 144      // attgemm tile pitch (64 fp16 cols)

// ---- scratch (device globals; no runtime allocations) ----
__device__ __align__(16) float g_E1[M_TOT], g_E1p[M_TOT], g_E2[M_TOT], g_E2p[M_TOT];
__device__ __align__(16) float g_wa1[FF], g_wa2[FF];
__device__ __align__(16) float g_Z[M_TOT];                 // atomically accumulated Z
__device__ __align__(16) uint32 g_mask[64*M_TOT];          // adj bitmask [b][iword(64)][j]
// h^T fp16, [b][o][word]: word w of 16-group grp packs (j, j+8), j = grp*16 + (w&7)
__device__ __align__(16) unsigned int g_hT16[M_TOT*FF/2];  // 8 MB
__device__ __align__(16) unsigned int g_WT16[FF*FF/2];     // W^T fp16 [n][k-pairs]

// ================= helpers =================
__device__ __forceinline__ uint32 smem_u32(const void* p){
    uint32 a; asm("{ .reg .u64 t; cvta.to.shared.u64 t, %1; cvt.u32.u64 %0, t; }" : "=r"(a) : "l"(p));
    return a;
}
__device__ __forceinline__ uint32 pack_f16x2(float a, float b){
    uint32 r; asm("cvt.rn.f16x2.f32 %0, %1, %2;" : "=r"(r) : "f"(b), "f"(a)); return r;
}
__device__ __forceinline__ void sts32(uint32 addr, uint32 v){
    asm volatile("st.shared.b32 [%0], %1;" :: "r"(addr), "r"(v) : "memory");
}
__device__ __forceinline__ void sts64(uint32 addr, uint32 a, uint32 b){
    asm volatile("st.shared.v2.b32 [%0], {%1,%2};" :: "r"(addr), "r"(a), "r"(b) : "memory");
}
__device__ __forceinline__ void sts128(uint32 addr, uint4 v){
    asm volatile("st.shared.v4.b32 [%0], {%1,%2,%3,%4};"
        :: "r"(addr), "r"(v.x), "r"(v.y), "r"(v.z), "r"(v.w) : "memory");
}
__device__ __forceinline__ void ldm4(uint32* r, uint32 addr){
    asm volatile("ldmatrix.sync.aligned.m8n8.x4.shared.b16 {%0,%1,%2,%3}, [%4];"
        : "=r"(r[0]), "=r"(r[1]), "=r"(r[2]), "=r"(r[3]) : "r"(addr));
}
__device__ __forceinline__ void mma_f16(float* c, const uint32* a, uint32 b0, uint32 b1){
    asm volatile("mma.sync.aligned.m16n8k16.row.col.f32.f16.f16.f32 "
        "{%0,%1,%2,%3}, {%4,%5,%6,%7}, {%8,%9}, {%0,%1,%2,%3};"
        : "+f"(c[0]), "+f"(c[1]), "+f"(c[2]), "+f"(c[3])
        : "r"(a[0]), "r"(a[1]), "r"(a[2]), "r"(a[3]), "r"(b0), "r"(b1));
}
__device__ __forceinline__ void cpa16(uint32 dst, const void* src){
    asm volatile("cp.async.cg.shared.global [%0], [%1], 16;" :: "r"(dst), "l"(src) : "memory");
}
#define CPA_COMMIT() asm volatile("cp.async.commit_group;" ::: "memory")
#define CPA_WAIT0()  asm volatile("cp.async.wait_group 0;" ::: "memory")

// ============================================================
// prep: [bx<128] W -> W^T fp16 ; [bx>=128] Wa matvecs. ALL: zero g_Z.
// ============================================================
__global__ void prep_kernel(const float* __restrict__ W, const float* __restrict__ a)
{
    const int bx = blockIdx.x, tid = threadIdx.x;
    int zi = bx * 256 + tid;
    if (zi < M_TOT) g_Z[zi] = 0.f;
    if (bx < 128) {
        int idx = bx * 256 + tid;
        int n = idx >> 7, kp = idx & 127;
        float v0 = W[(size_t)(2*kp)   * FF + n];
        float v1 = W[(size_t)(2*kp+1) * FF + n];
        g_WT16[n*128 + kp] = pack_f16x2(v0, v1);
    } else {
        int w = tid >> 5, lane = tid & 31;
        int k = (bx - 128) * 8 + w;
        float s1 = 0.f, s2 = 0.f;
        #pragma unroll
        for (int q = 0; q < 8; q++) {
            int e = lane + 32 * q;
            float v = __ldg(&W[(size_t)k * FF + e]);
            s1 += v * __ldg(&a[e]);
            s2 += v * __ldg(&a[256 + e]);
        }
        #pragma unroll
        for (int o = 16; o > 0; o >>= 1) {
            s1 += __shfl_xor_sync(0xffffffffu, s1, o);
            s2 += __shfl_xor_sync(0xffffffffu, s2, o);
        }
        if (lane == 0) { g_wa1[k] = s1; g_wa2[k] = s2; }
    }
}

// ============================================================
// sexp: s1[m] = x[m,:].Wa1 (fp32), exp tables. warp/row, float4 loads.
// ============================================================
__global__ void sexp_kernel(const float* __restrict__ x)
{
    __shared__ float4 swa[128];
    const int tid = threadIdx.x, warp = tid >> 5, lane = tid & 31;
    if (tid < 64)       swa[tid] = ((const float4*)g_wa1)[tid];
    else if (tid < 128) swa[tid] = ((const float4*)g_wa2)[tid - 64];
    __syncthreads();
    int row = blockIdx.x * 8 + warp;
    const float4* xr = (const float4*)(x + (size_t)row * FF);
    float4 a0 = __ldg(&xr[lane*2]), a1 = __ldg(&xr[lane*2 + 1]);
    float4 w0 = swa[lane*2],      w1 = swa[lane*2 + 1];
    float4 v0 = swa[64 + lane*2], v1 = swa[64 + lane*2 + 1];
    float s1 = a0.x*w0.x + a0.y*w0.y + a0.z*w0.z + a0.w*w0.w
             + a1.x*w1.x + a1.y*w1.y + a1.z*w1.z + a1.w*w1.w;
    float s2 = a0.x*v0.x + a0.y*v0.y + a0.z*v0.z + a0.w*v0.w
             + a1.x*v1.x + a1.y*v1.y + a1.z*v1.z + a1.w*v1.w;
    #pragma unroll
    for (int o = 16; o > 0; o >>= 1) {
        s1 += __shfl_xor_sync(0xffffffffu, s1, o);
        s2 += __shfl_xor_sync(0xffffffffu, s2, o);
    }
    if (lane == 0) {
        g_E1[row]  = __expf(s1);  g_E1p[row] = __expf(0.2f * s1);
        g_E2[row]  = __expf(s2);  g_E2p[row] = __expf(0.2f * s2);
    }
}

// ============================================================
// fused_zg: role by blockIdx%3. 768 blocks x 256 thr.
//   role 0,1 (512 CTAs): zpass — Z via RED.F32 + mask, 8 j/thread
//   role 2   (256 CTAs): gemm1 — h = x@W fp16 HMMA + hT16 epilogue
// ============================================================
__global__ __launch_bounds__(256,2) void fused_zg(
    const float* __restrict__ x, const int* __restrict__ adj)
{
    __shared__ __align__(16) unsigned char shm[25600];
    const int bx = blockIdx.x, tid = threadIdx.x;
    const int role = bx % 3;

    if (role != 2) {
        // ---------------- zpass role ----------------
        float2* sE = (float2*)shm;          // 32 entries
        const int z = (bx / 3) * 2 + role;  // 0..511
        const int iseg = z & 63, b = z >> 6;
        const int ibase = iseg * 32;
        if (tid < 32)
            sE[tid] = make_float2(g_E1[b*NN + ibase + tid], g_E1p[b*NN + ibase + tid]);
        __syncthreads();
        const int j8 = tid * 8;
        float4 e0 = *(const float4*)&g_E2[b*NN + j8];
        float4 e1 = *(const float4*)&g_E2[b*NN + j8 + 4];
        float4 p0 = *(const float4*)&g_E2p[b*NN + j8];
        float4 p1 = *(const float4*)&g_E2p[b*NN + j8 + 4];
        float r[8];
        r[0] = __fdividef(p0.x, e0.x); r[1] = __fdividef(p0.y, e0.y);
        r[2] = __fdividef(p0.z, e0.z); r[3] = __fdividef(p0.w, e0.w);
        r[4] = __fdividef(p1.x, e1.x); r[5] = __fdividef(p1.y, e1.y);
        r[6] = __fdividef(p1.z, e1.z); r[7] = __fdividef(p1.w, e1.w);
        const int4* ap = (const int4*)(adj + (size_t)(b*NN + ibase) * NN) + (j8 >> 2);
        float zz[8]; uint32 mm[8];
        #pragma unroll
        for (int k = 0; k < 8; k++) { zz[k] = 0.f; mm[k] = 0u; }
        #pragma unroll 4
        for (int il = 0; il < 32; il++) {
            int4 av0 = __ldg(&ap[(size_t)il * (NN/4)]);
            int4 av1 = __ldg(&ap[(size_t)il * (NN/4) + 1]);
            float2 E = sE[il];
            int av[8] = {av0.x, av0.y, av0.z, av0.w, av1.x, av1.y, av1.z, av1.w};
            #pragma unroll
            for (int k = 0; k < 8; k++) {
                float q = fmaxf(E.x, r[k] * E.y);
                mm[k] |= (uint32)av[k] << il;
                if (av[k]) zz[k] += q;
            }
        }
        float es[8] = {e0.x, e0.y, e0.z, e0.w, e1.x, e1.y, e1.z, e1.w};
        #pragma unroll
        for (int k = 0; k < 8; k++)
            atomicAdd(&g_Z[b*NN + j8 + k], zz[k] * es[k]);
        uint32* mp = &g_mask[((size_t)b*64 + iseg) * NN + j8];
        *(uint4*)mp       = make_uint4(mm[0], mm[1], mm[2], mm[3]);
        *(uint4*)(mp + 4) = make_uint4(mm[4], mm[5], mm[6], mm[7]);
        return;
    }

    // ---------------- gemm1 role ----------------
    const uint32 A = smem_u32(shm);            // 64*80 = 5120
    const uint32 B = A + 5120;                 // 256*80 = 20480
    const int lane = tid & 31, wid = tid >> 5;
    const int m0 = (bx / 3) * 64;
    const int iw = (wid & 1) * 32, ow = (wid >> 1) * 64;

    float c[2][8][4];
    #pragma unroll
    for (int u = 0; u < 2; u++)
        #pragma unroll
        for (int v = 0; v < 8; v++)
            #pragma unroll
            for (int d = 0; d < 4; d++) c[u][v][d] = 0.f;

    const int arow = tid >> 3, af4 = tid & 7;
    const uint4* wt = (const uint4*)g_WT16;
    float4 xa[2]; uint4 wb[4];

    #pragma unroll
    for (int p = 0; p < 2; p++)
        xa[p] = *(const float4*)&x[(size_t)(m0 + arow + p*32) * 256 + af4*4];
    #pragma unroll
    for (int p = 0; p < 4; p++) {
        int q = tid + p * 256;
        wb[p] = __ldg(&wt[(size_t)(q >> 2) * 32 + (q & 3)]);
    }

    for (int kt = 0; kt < 256; kt += 32) {
        __syncthreads();
        #pragma unroll
        for (int p = 0; p < 2; p++) {
            float4 v = xa[p];
            sts64(A + (uint32)(arow + p*32) * PITCH + af4 * 8,
                  pack_f16x2(v.x, v.y), pack_f16x2(v.z, v.w));
        }
        #pragma unroll
        for (int p = 0; p < 4; p++) {
            int q = tid + p * 256;
            sts128(B + (uint32)(q >> 2) * PITCH + (q & 3) * 16, wb[p]);
        }
        __syncthreads();
        if (kt < 224) {
            #pragma unroll
            for (int p = 0; p < 2; p++)
                xa[p] = *(const float4*)&x[(size_t)(m0 + arow + p*32) * 256 + kt + 32 + af4*4];
            #pragma unroll
            for (int p = 0; p < 4; p++) {
                int q = tid + p * 256;
                wb[p] = __ldg(&wt[(size_t)(q >> 2) * 32 + ((kt + 32) >> 3) + (q & 3)]);
            }
        }
        const uint32 base_off = (uint32)(lane & 15) * PITCH + (uint32)(lane >> 4) * 16;
        #pragma unroll
        for (int ks = 0; ks < 2; ks++) {
            const uint32 off = base_off + ks * 32;
            uint32 A0[4], A1[4], Bt[4][4];
            ldm4(A0, A + (uint32)iw * PITCH + off);
            ldm4(A1, A + (uint32)(iw + 16) * PITCH + off);
            #pragma unroll
            for (int t = 0; t < 4; t++) ldm4(Bt[t], B + (uint32)(ow + t*16) * PITCH + off);
            #pragma unroll
            for (int t = 0; t < 4; t++) {
                mma_f16(c[0][t*2+0], A0, Bt[t][0], Bt[t][2]);
                mma_f16(c[1][t*2+0], A1, Bt[t][0], Bt[t][2]);
                mma_f16(c[0][t*2+1], A0, Bt[t][1], Bt[t][3]);
                mma_f16(c[1][t*2+1], A1, Bt[t][1], Bt[t][3]);
            }
        }
    }

    const int g = lane >> 2, cq = (lane & 3) * 2;
    const int bb = m0 >> 11;
    const int jb = (m0 & 2047) + iw;
    #pragma unroll
    for (int mt = 0; mt < 2; mt++) {
        uint32 pidx = (uint32)((jb + mt*16) >> 4) * 8 + g;
        #pragma unroll
        for (int nt = 0; nt < 8; nt++) {
            int n = ow + nt*8 + cq;
            g_hT16[((size_t)(bb*FF + n))   * 1024 + pidx] = pack_f16x2(c[mt][nt][0], c[mt][nt][2]);
            g_hT16[((size_t)(bb*FF + n+1)) * 1024 + pidx] = pack_f16x2(c[mt][nt][1], c[mt][nt][3]);
        }
    }
}

// ============================================================
// attgemm: 128i x 256o per CTA, 512 thr, 1 CTA/SM.
// fp16 single-pass, BJ=64 chunks, bitmask adj, cp.async double-buffer.
// u2 computed on the fly from g_Z / g_E2 / g_E2p (zreduce eliminated).
// grid (16 itile, 8 b).
// ============================================================
#define ST_B   18432                 // 128*PITCH2
#define STAGE  55296                 // ST_B + 256*PITCH2

__global__ __launch_bounds__(512,1) void attgemm_mma(float* __restrict__ out)
{
    extern __shared__ __align__(16) unsigned char dsm[];
    __shared__ float2 sE1[128];
    const uint32 sb = smem_u32(dsm);
    const int tid = threadIdx.x, lane = tid & 31, wid = tid >> 5;
    const int b = blockIdx.y, i0 = blockIdx.x * 128;
    const int iw = (wid & 3) * 32, ow = (wid >> 2) * 64;

    if (tid < 128)
        sE1[tid] = make_float2(g_E1[b*NN + i0 + tid], g_E1p[b*NN + i0 + tid]);

    float c[2][8][4];
    #pragma unroll
    for (int u = 0; u < 2; u++)
        #pragma unroll
        for (int v = 0; v < 8; v++)
            #pragma unroll
            for (int d = 0; d < 4; d++) c[u][v][d] = 0.f;

    const int jp   = tid & 31;
    const int joff = ((jp >> 3) << 4) | (jp & 7);
    const int irow = tid >> 5;
    const uint32 adst = (uint32)irow * PITCH2 + jp * 4;
    const uint4* bbase = (const uint4*)g_hT16 + ((size_t)(b*FF + (tid >> 3))) * 256 + (tid & 7);
    const uint32 bd0 = ST_B + (uint32)(tid >> 3) * PITCH2 + (uint32)(tid & 7) * 16;
    const uint32* mbase = g_mask + ((size_t)b*64 + (i0 >> 5)) * NN + joff;
    const float* zb  = g_Z   + (size_t)b * NN + joff;
    const float* e2b = g_E2  + (size_t)b * NN + joff;
    const float* epb = g_E2p + (size_t)b * NN + joff;

    uint32 mlo[4], mhi[4]; float2 ulo, uhi;

    {
        #pragma unroll
        for (int p = 0; p < 4; p++) cpa16(sb + bd0 + p*9216, bbase + p*16384);
        CPA_COMMIT();
        #pragma unroll
        for (int w = 0; w < 4; w++) {
            mlo[w] = __ldg(&mbase[(size_t)w * NN]);
            mhi[w] = __ldg(&mbase[(size_t)w * NN + 8]);
        }
        float izl = __fdividef(1.f, __ldg(&zb[0]));
        float izh = __fdividef(1.f, __ldg(&zb[8]));
        ulo = make_float2(__ldg(&e2b[0]) * izl, __ldg(&epb[0]) * izl);
        uhi = make_float2(__ldg(&e2b[8]) * izh, __ldg(&epb[8]) * izh);
        __syncthreads();
        #pragma unroll
        for (int it = 0; it < 8; it++) {
            int w = it >> 1, bp = irow + (it & 1) * 16;
            uint32 bl = (mlo[w] >> bp) & 1;
            uint32 bh = (mhi[w] >> bp) & 1;
            float2 E = sE1[irow + it*16];
            float wl = bl ? fmaxf(E.x * ulo.x, E.y * ulo.y) : 0.f;
            float wh = bh ? fmaxf(E.x * uhi.x, E.y * uhi.y) : 0.f;
            sts32(sb + adst + (uint32)(it*16) * PITCH2, pack_f16x2(wl, wh));
        }
        CPA_WAIT0();
        __syncthreads();
    }

    for (int cc = 0; cc < 32; cc++) {
        const int s = cc & 1;
        const uint32 stg  = sb + (uint32)s * STAGE;
        const uint32 stg1 = sb + (uint32)(s ^ 1) * STAGE;
        if (cc < 31) {
            const int j1 = (cc + 1) * 64;
            #pragma unroll
            for (int p = 0; p < 4; p++) cpa16(stg1 + bd0 + p*9216, bbase + p*16384 + (j1 >> 3));
            CPA_COMMIT();
            #pragma unroll
            for (int w = 0; w < 4; w++) {
                mlo[w] = __ldg(&mbase[(size_t)w * NN + j1]);
                mhi[w] = __ldg(&mbase[(size_t)w * NN + j1 + 8]);
            }
            float izl = __fdividef(1.f, __ldg(&zb[j1]));
            float izh = __fdividef(1.f, __ldg(&zb[j1 + 8]));
            ulo = make_float2(__ldg(&e2b[j1]) * izl,     __ldg(&epb[j1]) * izl);
            uhi = make_float2(__ldg(&e2b[j1 + 8]) * izh, __ldg(&epb[j1 + 8]) * izh);
        }
        {
            const uint32 base_off = (uint32)(lane & 15) * PITCH2 + (uint32)(lane >> 4) * 16;
            #pragma unroll
            for (int ks = 0; ks < 4; ks++) {
                const uint32 off = base_off + ks * 32;
                uint32 A0[4], A1[4], Bt[4][4];
                ldm4(A0, stg + (uint32)iw * PITCH2 + off);
                ldm4(A1, stg + (uint32)(iw + 16) * PITCH2 + off);
                #pragma unroll
                for (int t = 0; t < 4; t++)
                    ldm4(Bt[t], stg + ST_B + (uint32)(ow + t*16) * PITCH2 + off);
                #pragma unroll
                for (int t = 0; t < 4; t++) {
                    mma_f16(c[0][t*2+0], A0, Bt[t][0], Bt[t][2]);
                    mma_f16(c[1][t*2+0], A1, Bt[t][0], Bt[t][2]);
                    mma_f16(c[0][t*2+1], A0, Bt[t][1], Bt[t][3]);
                    mma_f16(c[1][t*2+1], A1, Bt[t][1], Bt[t][3]);
                }
            }
        }
        if (cc < 31) {
            #pragma unroll
            for (int it = 0; it < 8; it++) {
                int w = it >> 1, bp = irow + (it & 1) * 16;
                uint32 bl = (mlo[w] >> bp) & 1;
                uint32 bh = (mhi[w] >> bp) & 1;
                float2 E = sE1[irow + it*16];
                float wl = bl ? fmaxf(E.x * ulo.x, E.y * ulo.y) : 0.f;
                float wh = bh ? fmaxf(E.x * uhi.x, E.y * uhi.y) : 0.f;
                sts32(stg1 + adst + (uint32)(it*16) * PITCH2, pack_f16x2(wl, wh));
            }
            CPA_WAIT0();
        }
        __syncthreads();
    }

    const int g = lane >> 2, cq = (lane & 3) * 2;
    #pragma unroll
    for (int mt = 0; mt < 2; mt++)
        #pragma unroll
        for (int nt = 0; nt < 8; nt++) {
            int i = i0 + iw + mt*16 + g;
            int o = ow + nt*8 + cq;
            float f0 = c[mt][nt][0], f1 = c[mt][nt][1];
            float f2 = c[mt][nt][2], f3 = c[mt][nt][3];
            f0 = f0 > 0.f ? f0 : expm1f(f0);
            f1 = f1 > 0.f ? f1 : expm1f(f1);
            f2 = f2 > 0.f ? f2 : expm1f(f2);
            f3 = f3 > 0.f ? f3 : expm1f(f3);
            *(float2*)&out[((size_t)(b*NN + i))   * FF + o] = make_float2(f0, f1);
            *(float2*)&out[((size_t)(b*NN + i+8)) * FF + o] = make_float2(f2, f3);
        }
}

extern "C" void kernel_launch(void* const* d_in, const int* in_sizes, int n_in,
                              void* d_out, int out_size)
{
    const float* x   = (const float*)d_in[0];
    const int*   adj = (const int*)d_in[1];
    const float* W   = (const float*)d_in[2];
    const float* a   = (const float*)d_in[3];
    float* out = (float*)d_out;

    cudaFuncSetAttribute(attgemm_mma, cudaFuncAttributeMaxDynamicSharedMemorySize, 2*STAGE);

    prep_kernel<<<160, 256>>>(W, a);
    sexp_kernel<<<2048, 256>>>(x);
    fused_zg<<<768, 256>>>(x, adj);
    attgemm_mma<<<dim3(16, 8), 512, 2*STAGE>>>(out);
}

// round 16
// speedup vs baseline: 1.1473x; 1.1473x over previous
#include <cuda_runtime.h>
#include <cuda_fp16.h>

typedef unsigned int uint32;

#define BB 8
#define NN 2048
#define FF 256
#define M_TOT (BB*NN)   // 16384
#define PITCH 80        // gemm1 tile pitch (32 fp16 cols)
#define PITCH2 272      // attgemm tile pitch (128 fp16 cols)

// ---- scratch (device globals; no runtime allocations) ----
__device__ __align__(16) float g_E1[M_TOT], g_E1p[M_TOT], g_E2[M_TOT], g_E2p[M_TOT];
__device__ __align__(16) float g_wa1[FF], g_wa2[FF];
__device__ __align__(16) float g_Zp[64*M_TOT];             // 4 MB partials
__device__ __align__(16) float2 g_u2[M_TOT];               // (E2*invZ, E2p*invZ)
__device__ __align__(16) uint32 g_mask[64*M_TOT];          // adj bitmask [b][iword(64)][j]
// h^T fp16, [b][o][word]: word w of 16-group grp packs (j, j+8), j = grp*16 + (w&7)
__device__ __align__(16) unsigned int g_hT16[M_TOT*FF/2];  // 8 MB
__device__ __align__(16) unsigned int g_WT16[FF*FF/2];     // W^T fp16 [n][k-pairs]

// ================= helpers =================
__device__ __forceinline__ uint32 smem_u32(const void* p){
    uint32 a; asm("{ .reg .u64 t; cvta.to.shared.u64 t, %1; cvt.u32.u64 %0, t; }" : "=r"(a) : "l"(p));
    return a;
}
__device__ __forceinline__ uint32 pack_f16x2(float a, float b){
    uint32 r; asm("cvt.rn.f16x2.f32 %0, %1, %2;" : "=r"(r) : "f"(b), "f"(a)); return r;
}
__device__ __forceinline__ void sts32(uint32 addr, uint32 v){
    asm volatile("st.shared.b32 [%0], %1;" :: "r"(addr), "r"(v) : "memory");
}
__device__ __forceinline__ void sts64(uint32 addr, uint32 a, uint32 b){
    asm volatile("st.shared.v2.b32 [%0], {%1,%2};" :: "r"(addr), "r"(a), "r"(b) : "memory");
}
__device__ __forceinline__ void sts128(uint32 addr, uint4 v){
    asm volatile("st.shared.v4.b32 [%0], {%1,%2,%3,%4};"
        :: "r"(addr), "r"(v.x), "r"(v.y), "r"(v.z), "r"(v.w) : "memory");
}
__device__ __forceinline__ void ldm4(uint32* r, uint32 addr){
    asm volatile("ldmatrix.sync.aligned.m8n8.x4.shared.b16 {%0,%1,%2,%3}, [%4];"
        : "=r"(r[0]), "=r"(r[1]), "=r"(r[2]), "=r"(r[3]) : "r"(addr));
}
__device__ __forceinline__ void mma_f16(float* c, const uint32* a, uint32 b0, uint32 b1){
    asm volatile("mma.sync.aligned.m16n8k16.row.col.f32.f16.f16.f32 "
        "{%0,%1,%2,%3}, {%4,%5,%6,%7}, {%8,%9}, {%0,%1,%2,%3};"
        : "+f"(c[0]), "+f"(c[1]), "+f"(c[2]), "+f"(c[3])
        : "r"(a[0]), "r"(a[1]), "r"(a[2]), "r"(a[3]), "r"(b0), "r"(b1));
}
__device__ __forceinline__ void cpa16(uint32 dst, const void* src){
    asm volatile("cp.async.cg.shared.global [%0], [%1], 16;" :: "r"(dst), "l"(src) : "memory");
}
#define CPA_COMMIT() asm volatile("cp.async.commit_group;" ::: "memory")
#define CPA_WAIT0()  asm volatile("cp.async.wait_group 0;" ::: "memory")

// ============================================================
// prep: [bx<128] W -> W^T fp16 ; [bx>=128] Wa1/Wa2 matvecs (fp32)
// ============================================================
__global__ void prep_kernel(const float* __restrict__ W, const float* __restrict__ a)
{
    const int bx = blockIdx.x, tid = threadIdx.x;
    if (bx < 128) {
        int idx = bx * 256 + tid;
        int n = idx >> 7, kp = idx & 127;
        float v0 = W[(size_t)(2*kp)   * FF + n];
        float v1 = W[(size_t)(2*kp+1) * FF + n];
        g_WT16[n*128 + kp] = pack_f16x2(v0, v1);
    } else {
        int w = tid >> 5, lane = tid & 31;
        int k = (bx - 128) * 8 + w;
        float s1 = 0.f, s2 = 0.f;
        #pragma unroll
        for (int q = 0; q < 8; q++) {
            int e = lane + 32 * q;
            float v = __ldg(&W[(size_t)k * FF + e]);
            s1 += v * __ldg(&a[e]);
            s2 += v * __ldg(&a[256 + e]);
        }
        #pragma unroll
        for (int o = 16; o > 0; o >>= 1) {
            s1 += __shfl_xor_sync(0xffffffffu, s1, o);
            s2 += __shfl_xor_sync(0xffffffffu, s2, o);
        }
        if (lane == 0) { g_wa1[k] = s1; g_wa2[k] = s2; }
    }
}

// ============================================================
// sexp: s1[m] = x[m,:].Wa1 (fp32), exp tables. warp/row, float4 loads.
// ============================================================
__global__ void sexp_kernel(const float* __restrict__ x)
{
    __shared__ float4 swa[128];
    const int tid = threadIdx.x, warp = tid >> 5, lane = tid & 31;
    if (tid < 64)       swa[tid] = ((const float4*)g_wa1)[tid];
    else if (tid < 128) swa[tid] = ((const float4*)g_wa2)[tid - 64];
    __syncthreads();
    int row = blockIdx.x * 8 + warp;
    const float4* xr = (const float4*)(x + (size_t)row * FF);
    float4 a0 = __ldg(&xr[lane*2]), a1 = __ldg(&xr[lane*2 + 1]);
    float4 w0 = swa[lane*2],      w1 = swa[lane*2 + 1];
    float4 v0 = swa[64 + lane*2], v1 = swa[64 + lane*2 + 1];
    float s1 = a0.x*w0.x + a0.y*w0.y + a0.z*w0.z + a0.w*w0.w
             + a1.x*w1.x + a1.y*w1.y + a1.z*w1.z + a1.w*w1.w;
    float s2 = a0.x*v0.x + a0.y*v0.y + a0.z*v0.z + a0.w*v0.w
             + a1.x*v1.x + a1.y*v1.y + a1.z*v1.z + a1.w*v1.w;
    #pragma unroll
    for (int o = 16; o > 0; o >>= 1) {
        s1 += __shfl_xor_sync(0xffffffffu, s1, o);
        s2 += __shfl_xor_sync(0xffffffffu, s2, o);
    }
    if (lane == 0) {
        g_E1[row]  = __expf(s1);  g_E1p[row] = __expf(0.2f * s1);
        g_E2[row]  = __expf(s2);  g_E2p[row] = __expf(0.2f * s2);
    }
}

// ============================================================
// fused_zg: role by blockIdx%3. 768 blocks x 256 thr. (R14 config)
//   role 0,1 (512 CTAs): zpass — Z partials + mask, 8 j/thread, 32-i segs
//   role 2   (256 CTAs): gemm1 — h = x@W fp16 HMMA + hT16 epilogue
// ============================================================
__global__ __launch_bounds__(256,2) void fused_zg(
    const float* __restrict__ x, const int* __restrict__ adj)
{
    __shared__ __align__(16) unsigned char shm[25600];
    const int bx = blockIdx.x, tid = threadIdx.x;
    const int role = bx % 3;

    if (role != 2) {
        // ---------------- zpass role ----------------
        float2* sE = (float2*)shm;          // 32 entries
        const int z = (bx / 3) * 2 + role;  // 0..511
        const int iseg = z & 63, b = z >> 6;
        const int ibase = iseg * 32;
        if (tid < 32)
            sE[tid] = make_float2(g_E1[b*NN + ibase + tid], g_E1p[b*NN + ibase + tid]);
        __syncthreads();
        const int j8 = tid * 8;
        float4 e0 = *(const float4*)&g_E2[b*NN + j8];
        float4 e1 = *(const float4*)&g_E2[b*NN + j8 + 4];
        float4 p0 = *(const float4*)&g_E2p[b*NN + j8];
        float4 p1 = *(const float4*)&g_E2p[b*NN + j8 + 4];
        float r[8];
        r[0] = __fdividef(p0.x, e0.x); r[1] = __fdividef(p0.y, e0.y);
        r[2] = __fdividef(p0.z, e0.z); r[3] = __fdividef(p0.w, e0.w);
        r[4] = __fdividef(p1.x, e1.x); r[5] = __fdividef(p1.y, e1.y);
        r[6] = __fdividef(p1.z, e1.z); r[7] = __fdividef(p1.w, e1.w);
        const int4* ap = (const int4*)(adj + (size_t)(b*NN + ibase) * NN) + (j8 >> 2);
        float zz[8]; uint32 mm[8];
        #pragma unroll
        for (int k = 0; k < 8; k++) { zz[k] = 0.f; mm[k] = 0u; }
        #pragma unroll 4
        for (int il = 0; il < 32; il++) {
            int4 av0 = __ldg(&ap[(size_t)il * (NN/4)]);
            int4 av1 = __ldg(&ap[(size_t)il * (NN/4) + 1]);
            float2 E = sE[il];
            int av[8] = {av0.x, av0.y, av0.z, av0.w, av1.x, av1.y, av1.z, av1.w};
            #pragma unroll
            for (int k = 0; k < 8; k++) {
                float q = fmaxf(E.x, r[k] * E.y);
                mm[k] |= (uint32)av[k] << il;
                if (av[k]) zz[k] += q;
            }
        }
        float* zp = &g_Zp[(size_t)iseg * M_TOT + b*NN + j8];
        *(float4*)zp       = make_float4(zz[0]*e0.x, zz[1]*e0.y, zz[2]*e0.z, zz[3]*e0.w);
        *(float4*)(zp + 4) = make_float4(zz[4]*e1.x, zz[5]*e1.y, zz[6]*e1.z, zz[7]*e1.w);
        uint32* mp = &g_mask[((size_t)b*64 + iseg) * NN + j8];
        *(uint4*)mp       = make_uint4(mm[0], mm[1], mm[2], mm[3]);
        *(uint4*)(mp + 4) = make_uint4(mm[4], mm[5], mm[6], mm[7]);
        return;
    }

    // ---------------- gemm1 role ----------------
    const uint32 A = smem_u32(shm);            // 64*80 = 5120
    const uint32 B = A + 5120;                 // 256*80 = 20480
    const int lane = tid & 31, wid = tid >> 5;
    const int m0 = (bx / 3) * 64;
    const int iw = (wid & 1) * 32, ow = (wid >> 1) * 64;

    float c[2][8][4];
    #pragma unroll
    for (int u = 0; u < 2; u++)
        #pragma unroll
        for (int v = 0; v < 8; v++)
            #pragma unroll
            for (int d = 0; d < 4; d++) c[u][v][d] = 0.f;

    const int arow = tid >> 3, af4 = tid & 7;
    const uint4* wt = (const uint4*)g_WT16;
    float4 xa[2]; uint4 wb[4];

    #pragma unroll
    for (int p = 0; p < 2; p++)
        xa[p] = *(const float4*)&x[(size_t)(m0 + arow + p*32) * 256 + af4*4];
    #pragma unroll
    for (int p = 0; p < 4; p++) {
        int q = tid + p * 256;
        wb[p] = __ldg(&wt[(size_t)(q >> 2) * 32 + (q & 3)]);
    }

    for (int kt = 0; kt < 256; kt += 32) {
        __syncthreads();
        #pragma unroll
        for (int p = 0; p < 2; p++) {
            float4 v = xa[p];
            sts64(A + (uint32)(arow + p*32) * PITCH + af4 * 8,
                  pack_f16x2(v.x, v.y), pack_f16x2(v.z, v.w));
        }
        #pragma unroll
        for (int p = 0; p < 4; p++) {
            int q = tid + p * 256;
            sts128(B + (uint32)(q >> 2) * PITCH + (q & 3) * 16, wb[p]);
        }
        __syncthreads();
        if (kt < 224) {
            #pragma unroll
            for (int p = 0; p < 2; p++)
                xa[p] = *(const float4*)&x[(size_t)(m0 + arow + p*32) * 256 + kt + 32 + af4*4];
            #pragma unroll
            for (int p = 0; p < 4; p++) {
                int q = tid + p * 256;
                wb[p] = __ldg(&wt[(size_t)(q >> 2) * 32 + ((kt + 32) >> 3) + (q & 3)]);
            }
        }
        const uint32 base_off = (uint32)(lane & 15) * PITCH + (uint32)(lane >> 4) * 16;
        #pragma unroll
        for (int ks = 0; ks < 2; ks++) {
            const uint32 off = base_off + ks * 32;
            uint32 A0[4], A1[4], Bt[4][4];
            ldm4(A0, A + (uint32)iw * PITCH + off);
            ldm4(A1, A + (uint32)(iw + 16) * PITCH + off);
            #pragma unroll
            for (int t = 0; t < 4; t++) ldm4(Bt[t], B + (uint32)(ow + t*16) * PITCH + off);
            #pragma unroll
            for (int t = 0; t < 4; t++) {
                mma_f16(c[0][t*2+0], A0, Bt[t][0], Bt[t][2]);
                mma_f16(c[1][t*2+0], A1, Bt[t][0], Bt[t][2]);
                mma_f16(c[0][t*2+1], A0, Bt[t][1], Bt[t][3]);
                mma_f16(c[1][t*2+1], A1, Bt[t][1], Bt[t][3]);
            }
        }
    }

    const int g = lane >> 2, cq = (lane & 3) * 2;
    const int bb = m0 >> 11;
    const int jb = (m0 & 2047) + iw;
    #pragma unroll
    for (int mt = 0; mt < 2; mt++) {
        uint32 pidx = (uint32)((jb + mt*16) >> 4) * 8 + g;
        #pragma unroll
        for (int nt = 0; nt < 8; nt++) {
            int n = ow + nt*8 + cq;
            g_hT16[((size_t)(bb*FF + n))   * 1024 + pidx] = pack_f16x2(c[mt][nt][0], c[mt][nt][2]);
            g_hT16[((size_t)(bb*FF + n+1)) * 1024 + pidx] = pack_f16x2(c[mt][nt][1], c[mt][nt][3]);
        }
    }
}

// ============================================================
// zreduce v2: 4-way parallel partial sums. 256 CTAs x 256 thr.
// ============================================================
__global__ __launch_bounds__(256) void zreduce_kernel()
{
    __shared__ float part[4][64];
    const int tid = threadIdx.x;
    const int idx = blockIdx.x * 64 + (tid & 63);
    const int sg  = tid >> 6;
    float z = 0.f;
    #pragma unroll
    for (int s = 0; s < 16; s++)
        z += g_Zp[(size_t)(sg * 16 + s) * M_TOT + idx];
    part[sg][tid & 63] = z;
    __syncthreads();
    if (tid < 64) {
        float t = part[0][tid] + part[1][tid] + part[2][tid] + part[3][tid];
        float iz = 1.0f / t;
        g_u2[idx] = make_float2(g_E2[idx] * iz, g_E2p[idx] * iz);
    }
}

// ============================================================
// attgemm v6: 128i x 256o per CTA, 512 thr, BJ=128 chunks (16 total)
// — halved barrier/prefetch episodes vs BJ=64. fp16 single-pass,
// bitmask adj, cp.async double-buffer. grid (16 itile, 8 b).
// ============================================================
#define ST_B   34816                 // 128*PITCH2
#define STAGE  104448                // ST_B + 256*PITCH2

__global__ __launch_bounds__(512,1) void attgemm_mma(float* __restrict__ out)
{
    extern __shared__ __align__(16) unsigned char dsm[];
    __shared__ float2 sE1[128];
    const uint32 sb = smem_u32(dsm);
    const int tid = threadIdx.x, lane = tid & 31, wid = tid >> 5;
    const int b = blockIdx.y, i0 = blockIdx.x * 128;
    const int iw = (wid & 3) * 32, ow = (wid >> 2) * 64;

    if (tid < 128)
        sE1[tid] = make_float2(g_E1[b*NN + i0 + tid], g_E1p[b*NN + i0 + tid]);

    float c[2][8][4];
    #pragma unroll
    for (int u = 0; u < 2; u++)
        #pragma unroll
        for (int v = 0; v < 8; v++)
            #pragma unroll
            for (int d = 0; d < 4; d++) c[u][v][d] = 0.f;

    // A-gen coords: word col jp (0..63), row group irow (0..7), i = irow + it*8
    const int jp   = tid & 63;
    const int joff = ((jp >> 3) << 4) | (jp & 7);      // j (lo of pair) in 0..127
    const int irow = tid >> 6;
    const uint32 adst = (uint32)irow * PITCH2 + jp * 4;
    // B cp.async: seg s2 (0..15), row orow (0..31), p 0..7 -> o = orow + p*32
    const int s2 = tid & 15, orow = tid >> 4;
    const uint4* bbase = (const uint4*)g_hT16 + ((size_t)(b*FF + orow)) * 256 + s2;
    const uint32 bd0 = ST_B + (uint32)orow * PITCH2 + (uint32)s2 * 16;
    const uint32* mbase = g_mask + ((size_t)b*64 + (i0 >> 5)) * NN + joff;
    const float2* u2b   = g_u2 + (size_t)b * NN + joff;

    uint32 mlo[4], mhi[4]; float2 ulo, uhi;

    // ---- prologue: chunk 0 into buffer 0 ----
    {
        #pragma unroll
        for (int p = 0; p < 8; p++) cpa16(sb + bd0 + p*8704u, bbase + p*8192);
        CPA_COMMIT();
        #pragma unroll
        for (int w = 0; w < 4; w++) {
            mlo[w] = __ldg(&mbase[(size_t)w * NN]);
            mhi[w] = __ldg(&mbase[(size_t)w * NN + 8]);
        }
        ulo = __ldg(&u2b[0]);         uhi = __ldg(&u2b[8]);
        __syncthreads();                  // sE1 ready
        #pragma unroll
        for (int it = 0; it < 16; it++) {
            int w = it >> 2, bp = irow + (it & 3) * 8;
            uint32 bl = (mlo[w] >> bp) & 1;
            uint32 bh = (mhi[w] >> bp) & 1;
            float2 E = sE1[irow + it*8];
            float wl = bl ? fmaxf(E.x * ulo.x, E.y * ulo.y) : 0.f;
            float wh = bh ? fmaxf(E.x * uhi.x, E.y * uhi.y) : 0.f;
            sts32(sb + adst + (uint32)(it*8) * PITCH2, pack_f16x2(wl, wh));
        }
        CPA_WAIT0();
        __syncthreads();
    }

    for (int cc = 0; cc < 16; cc++) {
        const int s = cc & 1;
        const uint32 stg  = sb + (uint32)s * STAGE;
        const uint32 stg1 = sb + (uint32)(s ^ 1) * STAGE;
        if (cc < 15) {
            const int j1 = (cc + 1) * 128;
            #pragma unroll
            for (int p = 0; p < 8; p++) cpa16(stg1 + bd0 + p*8704u, bbase + p*8192 + (j1 >> 3));
            CPA_COMMIT();
            #pragma unroll
            for (int w = 0; w < 4; w++) {
                mlo[w] = __ldg(&mbase[(size_t)w * NN + j1]);
                mhi[w] = __ldg(&mbase[(size_t)w * NN + j1 + 8]);
            }
            ulo = __ldg(&u2b[j1]);        uhi = __ldg(&u2b[j1 + 8]);
        }
        // MMA over 128-wide chunk: 8 ks
        {
            const uint32 base_off = (uint32)(lane & 15) * PITCH2 + (uint32)(lane >> 4) * 16;
            #pragma unroll
            for (int ks = 0; ks < 8; ks++) {
                const uint32 off = base_off + ks * 32;
                uint32 A0[4], A1[4], Bt[4][4];
                ldm4(A0, stg + (uint32)iw * PITCH2 + off);
                ldm4(A1, stg + (uint32)(iw + 16) * PITCH2 + off);
                #pragma unroll
                for (int t = 0; t < 4; t++)
                    ldm4(Bt[t], stg + ST_B + (uint32)(ow + t*16) * PITCH2 + off);
                #pragma unroll
                for (int t = 0; t < 4; t++) {
                    mma_f16(c[0][t*2+0], A0, Bt[t][0], Bt[t][2]);
                    mma_f16(c[1][t*2+0], A1, Bt[t][0], Bt[t][2]);
                    mma_f16(c[0][t*2+1], A0, Bt[t][1], Bt[t][3]);
                    mma_f16(c[1][t*2+1], A1, Bt[t][1], Bt[t][3]);
                }
            }
        }
        if (cc < 15) {
            #pragma unroll
            for (int it = 0; it < 16; it++) {
                int w = it >> 2, bp = irow + (it & 3) * 8;
                uint32 bl = (mlo[w] >> bp) & 1;
                uint32 bh = (mhi[w] >> bp) & 1;
                float2 E = sE1[irow + it*8];
                float wl = bl ? fmaxf(E.x * ulo.x, E.y * ulo.y) : 0.f;
                float wh = bh ? fmaxf(E.x * uhi.x, E.y * uhi.y) : 0.f;
                sts32(stg1 + adst + (uint32)(it*8) * PITCH2, pack_f16x2(wl, wh));
            }
            CPA_WAIT0();
        }
        __syncthreads();
    }

    // ---- epilogue: ELU + store ----
    const int g = lane >> 2, cq = (lane & 3) * 2;
    #pragma unroll
    for (int mt = 0; mt < 2; mt++)
        #pragma unroll
        for (int nt = 0; nt < 8; nt++) {
            int i = i0 + iw + mt*16 + g;
            int o = ow + nt*8 + cq;
            float f0 = c[mt][nt][0], f1 = c[mt][nt][1];
            float f2 = c[mt][nt][2], f3 = c[mt][nt][3];
            f0 = f0 > 0.f ? f0 : expm1f(f0);
            f1 = f1 > 0.f ? f1 : expm1f(f1);
            f2 = f2 > 0.f ? f2 : expm1f(f2);
            f3 = f3 > 0.f ? f3 : expm1f(f3);
            *(float2*)&out[((size_t)(b*NN + i))   * FF + o] = make_float2(f0, f1);
            *(float2*)&out[((size_t)(b*NN + i+8)) * FF + o] = make_float2(f2, f3);
        }
}

extern "C" void kernel_launch(void* const* d_in, const int* in_sizes, int n_in,
                              void* d_out, int out_size)
{
    const float* x   = (const float*)d_in[0];
    const int*   adj = (const int*)d_in[1];
    const float* W   = (const float*)d_in[2];
    const float* a   = (const float*)d_in[3];
    float* out = (float*)d_out;

    cudaFuncSetAttribute(attgemm_mma, cudaFuncAttributeMaxDynamicSharedMemorySize, 2*STAGE);

    prep_kernel<<<160, 256>>>(W, a);
    sexp_kernel<<<2048, 256>>>(x);
    fused_zg<<<768, 256>>>(x, adj);
    zreduce_kernel<<<256, 256>>>();
    attgemm_mma<<<dim3(16, 8), 512, 2*STAGE>>>(out);
}